// round 15
// baseline (speedup 1.0000x reference)
#include <cuda_runtime.h>
#include <cuda_fp16.h>
#include <cstdint>

// ---------------------------------------------------------------------------
// Problem constants
// ---------------------------------------------------------------------------
#define N_NODES 40000
#define N_EDGES 640000
#define D       128          // IN = HID = OUT = 128
#define D2      64           // half2 per row
#define DECD    64
#define TILE    128          // nodes per GEMM block
#define SAP     136          // smem half-stride (row pad for ldmatrix)

// ---------------------------------------------------------------------------
// Scratch (static device globals; no allocations allowed)
// ---------------------------------------------------------------------------
__device__ __half2 g_h0h[N_NODES * D2];    // dropout(x), fp16
__device__ __half2 g_h1h[N_NODES * D2];    // dropout(relu(layer1)), fp16
__device__ __half  g_aggh[N_NODES * D];    // aggregated, fp16 (GEMM A input)
__device__ float   g_logits[N_NODES * DECD];
__device__ int     g_degi[N_NODES];        // zeroed by scan_kernel each pass
__device__ int     g_rowptr[N_NODES + 1];
__device__ int     g_cursor[N_NODES];
__device__ int     g_esrc[N_EDGES];        // CSR-permuted source ids
__device__ double  g_acc;                  // reset by dec_kernel each pass
__device__ unsigned int g_ticket;          // self-resetting last-block ticket

struct alignas(8) h2x2 { __half2 a, b; };

// ---------------------------------------------------------------------------
// JAX-exact threefry2x32 (20 rounds), partitionable mode.
// ---------------------------------------------------------------------------
__host__ __device__ __forceinline__ void tf2x32(uint32_t k0, uint32_t k1,
                                                uint32_t x0, uint32_t x1,
                                                uint32_t* o0, uint32_t* o1) {
    uint32_t ks2 = k0 ^ k1 ^ 0x1BD11BDAu;
    x0 += k0; x1 += k1;
#define TF_RND(r) { x0 += x1; x1 = (x1 << (r)) | (x1 >> (32 - (r))); x1 ^= x0; }
    TF_RND(13) TF_RND(15) TF_RND(26) TF_RND(6)   x0 += k1;  x1 += ks2 + 1u;
    TF_RND(17) TF_RND(29) TF_RND(16) TF_RND(24)  x0 += ks2; x1 += k0  + 2u;
    TF_RND(13) TF_RND(15) TF_RND(26) TF_RND(6)   x0 += k0;  x1 += k1  + 3u;
    TF_RND(17) TF_RND(29) TF_RND(16) TF_RND(24)  x0 += k1;  x1 += ks2 + 4u;
    TF_RND(13) TF_RND(15) TF_RND(26) TF_RND(6)   x0 += ks2; x1 += k0  + 5u;
#undef TF_RND
    *o0 = x0; *o1 = x1;
}

// bits = out0 ^ out1 of threefry(key, (0, j)).  keep <=> bit31 == 0.
__device__ __forceinline__ uint32_t pbits(uint32_t k0, uint32_t k1, uint32_t j) {
    uint32_t o0, o1;
    tf2x32(k0, k1, 0u, j, &o0, &o1);
    return o0 ^ o1;
}

// ---------------------------------------------------------------------------
// Packed f32x2 helpers (FFMA2, used by logits GEMM)
// ---------------------------------------------------------------------------
__device__ __forceinline__ unsigned long long pk2(float lo, float hi) {
    unsigned long long r;
    asm("mov.b64 %0, {%1, %2};" : "=l"(r) : "f"(lo), "f"(hi));
    return r;
}
__device__ __forceinline__ void upk2(unsigned long long v, float& lo, float& hi) {
    asm("mov.b64 {%0, %1}, %2;" : "=f"(lo), "=f"(hi) : "l"(v));
}
__device__ __forceinline__ void fma2(unsigned long long& d,
                                     unsigned long long a,
                                     unsigned long long b) {
    asm("fma.rn.f32x2 %0, %1, %2, %0;" : "+l"(d) : "l"(a), "l"(b));
}

// ---------------------------------------------------------------------------
// Tensor-core helpers (mma.sync m16n8k16 fp16 -> fp32)
// ---------------------------------------------------------------------------
__device__ __forceinline__ uint32_t smem_u32(const void* p) {
    return (uint32_t)__cvta_generic_to_shared(p);
}
__device__ __forceinline__ void ldsm_x4(uint32_t* r, uint32_t addr) {
    asm volatile("ldmatrix.sync.aligned.m8n8.x4.shared.b16 {%0,%1,%2,%3}, [%4];"
        : "=r"(r[0]), "=r"(r[1]), "=r"(r[2]), "=r"(r[3]) : "r"(addr));
}
__device__ __forceinline__ void ldsm_x2(uint32_t* r, uint32_t addr) {
    asm volatile("ldmatrix.sync.aligned.m8n8.x2.shared.b16 {%0,%1}, [%2];"
        : "=r"(r[0]), "=r"(r[1]) : "r"(addr));
}
__device__ __forceinline__ void mma16816(float* c, const uint32_t* a,
                                         const uint32_t* b) {
    asm volatile("mma.sync.aligned.m16n8k16.row.col.f32.f16.f16.f32 "
        "{%0,%1,%2,%3}, {%4,%5,%6,%7}, {%8,%9}, {%0,%1,%2,%3};"
        : "+f"(c[0]), "+f"(c[1]), "+f"(c[2]), "+f"(c[3])
        : "r"(a[0]), "r"(a[1]), "r"(a[2]), "r"(a[3]), "r"(b[0]), "r"(b[1]));
}

// ---------------------------------------------------------------------------
// deg: degree count (2 edges/thread)
// ---------------------------------------------------------------------------
__global__ void deg_kernel(const int* __restrict__ dst) {
    int t = blockIdx.x * blockDim.x + threadIdx.x;
    int e0 = t * 2;
    if (e0 >= N_EDGES) return;
    atomicAdd(&g_degi[__ldg(&dst[e0])], 1);
    if (e0 + 1 < N_EDGES) atomicAdd(&g_degi[__ldg(&dst[e0 + 1])], 1);
}

// ---------------------------------------------------------------------------
// scan: rowptr prefix sum; zeroes g_degi after reading (no memset needed).
// ---------------------------------------------------------------------------
__global__ void scan_kernel() {
    __shared__ int sh[1024];
    const int tid = threadIdx.x;
    const int per = 40;
    int base = tid * per;
    int deg_local[per];
    int s = 0;
    if (base < N_NODES) {
        #pragma unroll
        for (int i = 0; i < per; i += 4) {
            int4 d4 = *reinterpret_cast<const int4*>(&g_degi[base + i]);
            deg_local[i + 0] = d4.x; deg_local[i + 1] = d4.y;
            deg_local[i + 2] = d4.z; deg_local[i + 3] = d4.w;
            s += d4.x + d4.y + d4.z + d4.w;
        }
        int4 z = make_int4(0, 0, 0, 0);
        #pragma unroll
        for (int i = 0; i < per; i += 4)
            *reinterpret_cast<int4*>(&g_degi[base + i]) = z;
    }
    sh[tid] = s;
    __syncthreads();
    for (int o = 1; o < 1024; o <<= 1) {
        int v = (tid >= o) ? sh[tid - o] : 0;
        __syncthreads();
        sh[tid] += v;
        __syncthreads();
    }
    int run = (tid > 0) ? sh[tid - 1] : 0;
    if (base < N_NODES) {
        for (int i = 0; i < per; i++) {
            int v = base + i;
            g_rowptr[v] = run;
            g_cursor[v] = run;
            run += deg_local[i];
        }
        if (base + per >= N_NODES) g_rowptr[N_NODES] = run;
    }
}

// ---------------------------------------------------------------------------
// FAT kernel: blocks [0, 1250) = CSR slot fill (latency-bound);
//             blocks [1250, 3750) = dropout(x) -> g_h0h (ALU-bound).
// Disjoint pipes; the ~18us dropout hides the ~14us fill.
// ---------------------------------------------------------------------------
#define FILL_BLOCKS 1250
#define DROP_BLOCKS 2500

__global__ void fat_fill_drop_kernel(const int* __restrict__ src,
                                     const int* __restrict__ dst,
                                     const float* __restrict__ x,
                                     uint32_t k0, uint32_t k1) {
    if (blockIdx.x < FILL_BLOCKS) {
        int t = blockIdx.x * blockDim.x + threadIdx.x;
        int e0 = t * 2;
        if (e0 >= N_EDGES) return;
        int d0 = __ldg(&dst[e0]);
        int s0 = __ldg(&src[e0]);
        int slot0 = atomicAdd(&g_cursor[d0], 1);
        if (e0 + 1 < N_EDGES) {
            int d1 = __ldg(&dst[e0 + 1]);
            int s1 = __ldg(&src[e0 + 1]);
            int slot1 = atomicAdd(&g_cursor[d1], 1);
            g_esrc[slot1] = s1;
        }
        g_esrc[slot0] = s0;
    } else {
        int t = (blockIdx.x - FILL_BLOCKS) * blockDim.x + threadIdx.x;
        int j = t * 8;
        float4 v0 = *reinterpret_cast<const float4*>(x + j);
        float4 v1 = *reinterpret_cast<const float4*>(x + j + 4);
        float f[8] = {v0.x, v0.y, v0.z, v0.w, v1.x, v1.y, v1.z, v1.w};
        __half2 o[4];
        #pragma unroll
        for (int i = 0; i < 4; i++) {
            float a = (pbits(k0, k1, j + 2 * i)     & 0x80000000u) ? 0.0f : f[2 * i]     * 2.0f;
            float b = (pbits(k0, k1, j + 2 * i + 1) & 0x80000000u) ? 0.0f : f[2 * i + 1] * 2.0f;
            o[i] = __floats2half2_rn(a, b);
        }
        *reinterpret_cast<uint4*>(g_h0h + j / 2) =
            *reinterpret_cast<const uint4*>(o);
    }
}

// ---------------------------------------------------------------------------
// AGG kernel (smem-free, high occupancy):
//   agg[v] = (h[v] + sum_{u->v} h[u]) / (deg+1),  fp16 in, fp16 out (fp32 acc)
// One warp per node; lane covers k = 4*lane..4*lane+3.
// ---------------------------------------------------------------------------
__global__ void __launch_bounds__(256)
agg_kernel(const __half2* __restrict__ hin) {
    const int w    = (blockIdx.x * blockDim.x + threadIdx.x) >> 5;
    const int lane = threadIdx.x & 31;
    const int beg = __ldg(&g_rowptr[w]);
    const int end = __ldg(&g_rowptr[w + 1]);
    h2x2 sv = *reinterpret_cast<const h2x2*>(hin + (size_t)w * D2 + 2 * lane);
    float2 s0 = __half22float2(sv.a), s1 = __half22float2(sv.b);
    float4 acc = make_float4(s0.x, s0.y, s1.x, s1.y);
    int i = beg;
    for (; i + 7 < end; i += 8) {
        h2x2 m[8];
        #pragma unroll
        for (int u = 0; u < 8; u++) {
            int s = __ldg(&g_esrc[i + u]);
            m[u] = *reinterpret_cast<const h2x2*>(hin + (size_t)s * D2 + 2 * lane);
        }
        #pragma unroll
        for (int u = 0; u < 8; u++) {
            float2 f0 = __half22float2(m[u].a);
            float2 f1 = __half22float2(m[u].b);
            acc.x += f0.x; acc.y += f0.y;
            acc.z += f1.x; acc.w += f1.y;
        }
    }
    for (; i < end; i++) {
        int s = __ldg(&g_esrc[i]);
        h2x2 m0 = *reinterpret_cast<const h2x2*>(hin + (size_t)s * D2 + 2 * lane);
        float2 f0 = __half22float2(m0.a);
        float2 f1 = __half22float2(m0.b);
        acc.x += f0.x; acc.y += f0.y;
        acc.z += f1.x; acc.w += f1.y;
    }
    float rs = 1.0f / (float)(end - beg + 1);
    h2x2 st;
    st.a = __floats2half2_rn(acc.x * rs, acc.y * rs);
    st.b = __floats2half2_rn(acc.z * rs, acc.w * rs);
    *reinterpret_cast<h2x2*>(g_aggh + (size_t)w * D + 4 * lane) = st;
}

// ---------------------------------------------------------------------------
// Tensor-core layer GEMM:  out[v][c] = sum_k aggh[v][k] * W[c][k] + bias[c]
// Block 256 thr = 8 warps (4 m x 2 n), tile 128 nodes x 128 cols.
// A: fp16 smem [128][SAP]; W: fp32->fp16 smem [128][SAP] ([c][k] row-major
// == B col-major for mma.row.col).  fp32 accumulators (same k-order as TILE=64).
// ---------------------------------------------------------------------------
#define GEMM_SMEM ((128 * SAP + 128 * SAP) * 2)

template <int RELU_DROP>
__global__ void __launch_bounds__(256, 2)
gemm_layer_kernel(const float* __restrict__ W,
                  const float* __restrict__ bias,
                  float* __restrict__ out_f,
                  __half2* __restrict__ out_h,
                  uint32_t k0, uint32_t k1) {
    extern __shared__ __half smh[];
    __half* Ash = smh;                 // [128][SAP]
    __half* Wsh = smh + 128 * SAP;     // [128][SAP]

    const int tid    = threadIdx.x;
    const int lane   = tid & 31;
    const int wid    = tid >> 5;
    const int warp_m = wid >> 1;       // 0..3   (32 rows each)
    const int warp_n = wid & 1;        // 0..1   (64 cols each)
    const int base   = blockIdx.x * TILE;

    // W load: fp32 [c][k] -> fp16 smem (float4 -> 2x half2)
    #pragma unroll
    for (int idx = tid * 4; idx < 128 * 128; idx += 256 * 4) {
        float4 w4 = *reinterpret_cast<const float4*>(W + idx);
        int c = idx >> 7, k = idx & 127;
        __half2* p = reinterpret_cast<__half2*>(Wsh + c * SAP + k);
        p[0] = __floats2half2_rn(w4.x, w4.y);
        p[1] = __floats2half2_rn(w4.z, w4.w);
    }
    // A load: 128 rows x 128 halves from g_aggh (uint4 = 8 halves)
    #pragma unroll
    for (int idx = tid; idx < 128 * 16; idx += 256) {
        int r = idx >> 4, c8 = idx & 15;
        uint4 v = *reinterpret_cast<const uint4*>(
            g_aggh + (size_t)(base + r) * D + c8 * 8);
        *reinterpret_cast<uint4*>(Ash + r * SAP + c8 * 8) = v;
    }
    __syncthreads();

    float acc[2][8][4];
    #pragma unroll
    for (int s = 0; s < 2; s++)
        #pragma unroll
        for (int j = 0; j < 8; j++)
            #pragma unroll
            for (int q = 0; q < 4; q++) acc[s][j][q] = 0.0f;

    // ldmatrix base addresses (canonical fragment recipes)
    const int arow = warp_m * 32 + (lane & 15);
    const int acol = (lane >> 4) * 8;
    uint32_t a_addr = smem_u32(Ash + arow * SAP + acol);
    const int brow = warp_n * 64 + (lane & 7);
    const int bcol = ((lane >> 3) & 1) * 8;
    uint32_t b_addr = smem_u32(Wsh + brow * SAP + bcol);

    #pragma unroll
    for (int kt = 0; kt < 8; kt++) {          // K = 8 x 16
        uint32_t a[2][4], b[8][2];
        #pragma unroll
        for (int s = 0; s < 2; s++)
            ldsm_x4(a[s], a_addr + s * (16 * SAP * 2) + kt * 32);
        #pragma unroll
        for (int j = 0; j < 8; j++)
            ldsm_x2(b[j], b_addr + j * (8 * SAP * 2) + kt * 32);
        #pragma unroll
        for (int s = 0; s < 2; s++)
            #pragma unroll
            for (int j = 0; j < 8; j++)
                mma16816(acc[s][j], a[s], b[j]);
    }

    // Epilogue.  c-fragment: rows lane>>2 (+8), cols 2*(lane&3)+{0,1}.
    #pragma unroll
    for (int s = 0; s < 2; s++) {
        #pragma unroll
        for (int j = 0; j < 8; j++) {
            int cbase = warp_n * 64 + j * 8 + 2 * (lane & 3);
            float b0 = __ldg(&bias[cbase]);
            float b1 = __ldg(&bias[cbase + 1]);
            #pragma unroll
            for (int half = 0; half < 2; half++) {
                int v = base + warp_m * 32 + s * 16 + (lane >> 2) + half * 8;
                float r0 = acc[s][j][2 * half + 0] + b0;
                float r1 = acc[s][j][2 * half + 1] + b1;
                if (RELU_DROP) {
                    r0 = fmaxf(r0, 0.0f);
                    r1 = fmaxf(r1, 0.0f);
                    uint32_t j0 = (uint32_t)(v * D + cbase);
                    r0 = (pbits(k0, k1, j0 + 0) & 0x80000000u) ? 0.0f : r0 * 2.0f;
                    r1 = (pbits(k0, k1, j0 + 1) & 0x80000000u) ? 0.0f : r1 * 2.0f;
                    out_h[(size_t)v * D2 + cbase / 2] = __floats2half2_rn(r0, r1);
                } else {
                    *reinterpret_cast<float2*>(out_f + (size_t)v * D + cbase) =
                        make_float2(r0, r1);
                }
            }
        }
    }
}

// ---------------------------------------------------------------------------
// Standalone tiled GEMM (logits, NC=64, fp32 FFMA2; A = fp32 h output)
// ---------------------------------------------------------------------------
#define GEMM64_SMEM ((128 * 68 + 16 * 256) * 4)

__global__ void __launch_bounds__(128)
gemm64_kernel(const float* __restrict__ A,
              const float* __restrict__ W,
              const float* __restrict__ bias,
              float* __restrict__ out) {
    constexpr int NC = 64, NCP = 68, TXN = 16, NTHR = 128;
    extern __shared__ float sm[];
    float* Wt   = sm;                  // [128][68]
    float* AshF = sm + 128 * NCP;      // [16 pairs][128][2]
    const unsigned long long* AshU =
        reinterpret_cast<const unsigned long long*>(AshF);

    const int tid  = threadIdx.x;
    const int tx   = tid % TXN;
    const int ty   = tid / TXN;
    const int base = blockIdx.x * 32;

    for (int idx = tid; idx < NC * 128; idx += NTHR) {
        int c = idx >> 7, k = idx & 127;
        Wt[k * NCP + c] = W[idx];
    }
    for (int idx = tid; idx < 32 * 128; idx += NTHR) {
        int n = idx >> 7, k = idx & 127;
        AshF[(n >> 1) * 256 + 2 * k + (n & 1)] = A[(size_t)(base + n) * D + k];
    }
    __syncthreads();

    unsigned long long acc2[2][4];
    #pragma unroll
    for (int p = 0; p < 2; p++)
        #pragma unroll
        for (int j = 0; j < 4; j++) acc2[p][j] = 0ull;

    const int p0 = ty * 2;
    #pragma unroll 8
    for (int k = 0; k < 128; k += 4) {
        float4 wv[4];
        #pragma unroll
        for (int i = 0; i < 4; i++)
            wv[i] = *reinterpret_cast<const float4*>(&Wt[(k + i) * NCP + 4 * tx]);
        #pragma unroll
        for (int i = 0; i < 4; i++) {
            unsigned long long wd0 = pk2(wv[i].x, wv[i].x);
            unsigned long long wd1 = pk2(wv[i].y, wv[i].y);
            unsigned long long wd2 = pk2(wv[i].z, wv[i].z);
            unsigned long long wd3 = pk2(wv[i].w, wv[i].w);
            #pragma unroll
            for (int p = 0; p < 2; p++) {
                unsigned long long av = AshU[(p0 + p) * 128 + k + i];
                fma2(acc2[p][0], av, wd0);
                fma2(acc2[p][1], av, wd1);
                fma2(acc2[p][2], av, wd2);
                fma2(acc2[p][3], av, wd3);
            }
        }
    }

    float bias4[4];
    #pragma unroll
    for (int j = 0; j < 4; j++) bias4[j] = __ldg(&bias[4 * tx + j]);

    #pragma unroll
    for (int p = 0; p < 2; p++) {
        float lo[4], hi[4];
        #pragma unroll
        for (int j = 0; j < 4; j++) upk2(acc2[p][j], lo[j], hi[j]);
        #pragma unroll
        for (int half = 0; half < 2; half++) {
            int n = ty * 4 + 2 * p + half;
            int v = base + n;
            float4 r;
            float* vals = half ? hi : lo;
            r.x = vals[0] + bias4[0];
            r.y = vals[1] + bias4[1];
            r.z = vals[2] + bias4[2];
            r.w = vals[3] + bias4[3];
            *reinterpret_cast<float4*>(out + (size_t)v * NC + 4 * tx) = r;
        }
    }
}

// ---------------------------------------------------------------------------
// Decoder loss + fused finalize (last-block ticket; self-resets g_acc).
// ---------------------------------------------------------------------------
__global__ void dec_kernel(const int* __restrict__ shuf,
                           float* __restrict__ out) {
    __shared__ float warp_sums[8];
    int warp = threadIdx.x >> 5;
    int lane = threadIdx.x & 31;
    int v = blockIdx.x * 8 + warp;
    float contrib = 0.0f;
    if (v < N_NODES) {
        const float* a = g_logits + (size_t)v * DECD;
        float a0 = a[lane], a1 = a[lane + 32];
        float m = fmaxf(a0, a1);
        #pragma unroll
        for (int off = 16; off; off >>= 1)
            m = fmaxf(m, __shfl_xor_sync(0xffffffffu, m, off));
        float s = expf(a0 - m) + expf(a1 - m);
        #pragma unroll
        for (int off = 16; off; off >>= 1)
            s += __shfl_xor_sync(0xffffffffu, s, off);
        float lse = m + logf(s);
        const float* bp = g_logits + (size_t)__ldg(&shuf[v]) * DECD;
        float b0 = bp[lane], b1 = bp[lane + 32];
        float t = b0 * (a0 - lse) + b1 * (a1 - lse);
        #pragma unroll
        for (int off = 16; off; off >>= 1)
            t += __shfl_xor_sync(0xffffffffu, t, off);
        contrib = -t;
    }
    if (lane == 0) warp_sums[warp] = contrib;
    __syncthreads();
    if (threadIdx.x == 0) {
        float s = 0.0f;
        #pragma unroll
        for (int w = 0; w < 8; w++) s += warp_sums[w];
        atomicAdd(&g_acc, (double)s);
        __threadfence();
        unsigned int t = atomicAdd(&g_ticket, 1u);
        if (t == gridDim.x - 1) {
            out[(size_t)N_NODES * D] = (float)(g_acc / (double)N_NODES);
            g_acc = 0.0;               // self-reset for graph replay
            g_ticket = 0;
        }
    }
}

// ---------------------------------------------------------------------------
// Host launcher (graph-capturable).  Order: deg(1), scan(2),
// fat(fill||dropout)(3), agg(4), gemm1(5), agg(6), gemm2(7), logits(8), dec(9).
// ---------------------------------------------------------------------------
extern "C" void kernel_launch(void* const* d_in, const int* in_sizes, int n_in,
                              void* d_out, int out_size) {
    const float* x    = (const float*)d_in[0];
    const int*   src  = (const int*)  d_in[1];
    const int*   dst  = (const int*)  d_in[2];
    const int*   shuf = (const int*)  d_in[3];
    const float* W1   = (const float*)d_in[4];
    const float* b1   = (const float*)d_in[5];
    const float* W2   = (const float*)d_in[6];
    const float* b2   = (const float*)d_in[7];
    const float* Wd   = (const float*)d_in[8];
    const float* bd   = (const float*)d_in[9];
    float* out = (float*)d_out;

    // JAX partitionable threefry: split(key(42),2) foldlike.
    uint32_t dk0_k0, dk0_k1, dk1_k0, dk1_k1;
    tf2x32(0u, 42u, 0u, 0u, &dk0_k0, &dk0_k1);   // dropout on x
    tf2x32(0u, 42u, 0u, 1u, &dk1_k0, &dk1_k1);   // dropout after relu(layer1)

    void *p_h0h, *p_h1h, *p_logits;
    cudaGetSymbolAddress(&p_h0h,    g_h0h);
    cudaGetSymbolAddress(&p_h1h,    g_h1h);
    cudaGetSymbolAddress(&p_logits, g_logits);

    cudaFuncSetAttribute((const void*)gemm_layer_kernel<1>,
                         cudaFuncAttributeMaxDynamicSharedMemorySize, GEMM_SMEM);
    cudaFuncSetAttribute((const void*)gemm_layer_kernel<0>,
                         cudaFuncAttributeMaxDynamicSharedMemorySize, GEMM_SMEM);
    cudaFuncSetAttribute((const void*)gemm64_kernel,
                         cudaFuncAttributeMaxDynamicSharedMemorySize, GEMM64_SMEM);

    // 1: degree count (g_degi zeroed by previous scan run)
    deg_kernel<<<(N_EDGES / 2 + 255) / 256, 256>>>(dst);
    // 2: rowptr scan (also zeroes g_degi for next replay)
    scan_kernel<<<1, 1024>>>();
    // 3: CSR slot fill || dropout(x) -> g_h0h  (overlapped pipes)
    fat_fill_drop_kernel<<<FILL_BLOCKS + DROP_BLOCKS, 256>>>(
        src, dst, x, dk0_k0, dk0_k1);
    // 4: layer 1 aggregate -> g_aggh (fp16)
    agg_kernel<<<N_NODES / 8, 256>>>((const __half2*)p_h0h);
    // 5: layer 1 GEMM (tensor core) + relu + dropout -> g_h1h (fp16)
    gemm_layer_kernel<1><<<(N_NODES + TILE - 1) / TILE, 256, GEMM_SMEM>>>(
        W1, b1, nullptr, (__half2*)p_h1h, dk1_k0, dk1_k1);
    // 6: layer 2 aggregate
    agg_kernel<<<N_NODES / 8, 256>>>((const __half2*)p_h1h);
    // 7: layer 2 GEMM (tensor core) -> out (fp32)
    gemm_layer_kernel<0><<<(N_NODES + TILE - 1) / TILE, 256, GEMM_SMEM>>>(
        W2, b2, out, nullptr, 0u, 0u);
    // 8: logits
    gemm64_kernel<<<N_NODES / 32, 128, GEMM64_SMEM>>>(out, Wd, bd, (float*)p_logits);
    // 9: decoder loss + finalize (self-resets g_acc / g_ticket)
    dec_kernel<<<N_NODES / 8, 256>>>(shuf, out);
}

// round 16
// speedup vs baseline: 1.0398x; 1.0398x over previous
#include <cuda_runtime.h>
#include <cuda_fp16.h>
#include <cstdint>

// ---------------------------------------------------------------------------
// Problem constants
// ---------------------------------------------------------------------------
#define N_NODES 40000
#define N_EDGES 640000
#define D       128          // IN = HID = OUT = 128
#define D2      64           // half2 per row
#define DECD    64
#define TILE    64           // nodes per GEMM block (R14-proven; 625 blocks)
#define SAP     136          // smem half-stride (row pad for ldmatrix)

// ---------------------------------------------------------------------------
// Scratch (static device globals; no allocations allowed)
// ---------------------------------------------------------------------------
__device__ __half2 g_h0h[N_NODES * D2];    // dropout(x), fp16
__device__ __half2 g_h1h[N_NODES * D2];    // dropout(relu(layer1)), fp16
__device__ __half  g_aggh[N_NODES * D];    // aggregated, fp16 (GEMM A input)
__device__ float   g_logits[N_NODES * DECD];
__device__ int     g_degi[N_NODES];        // zeroed by scan_kernel each pass
__device__ int     g_rowptr[N_NODES + 1];
__device__ int     g_cursor[N_NODES];
__device__ int     g_esrc[N_EDGES];        // CSR-permuted source ids
__device__ double  g_acc;                  // reset by dec_kernel each pass
__device__ unsigned int g_ticket;          // self-resetting last-block ticket

struct alignas(8) h2x2 { __half2 a, b; };

// ---------------------------------------------------------------------------
// JAX-exact threefry2x32 (20 rounds), partitionable mode.
// ---------------------------------------------------------------------------
__host__ __device__ __forceinline__ void tf2x32(uint32_t k0, uint32_t k1,
                                                uint32_t x0, uint32_t x1,
                                                uint32_t* o0, uint32_t* o1) {
    uint32_t ks2 = k0 ^ k1 ^ 0x1BD11BDAu;
    x0 += k0; x1 += k1;
#define TF_RND(r) { x0 += x1; x1 = (x1 << (r)) | (x1 >> (32 - (r))); x1 ^= x0; }
    TF_RND(13) TF_RND(15) TF_RND(26) TF_RND(6)   x0 += k1;  x1 += ks2 + 1u;
    TF_RND(17) TF_RND(29) TF_RND(16) TF_RND(24)  x0 += ks2; x1 += k0  + 2u;
    TF_RND(13) TF_RND(15) TF_RND(26) TF_RND(6)   x0 += k0;  x1 += k1  + 3u;
    TF_RND(17) TF_RND(29) TF_RND(16) TF_RND(24)  x0 += k1;  x1 += ks2 + 4u;
    TF_RND(13) TF_RND(15) TF_RND(26) TF_RND(6)   x0 += ks2; x1 += k0  + 5u;
#undef TF_RND
    *o0 = x0; *o1 = x1;
}

// bits = out0 ^ out1 of threefry(key, (0, j)).  keep <=> bit31 == 0.
__device__ __forceinline__ uint32_t pbits(uint32_t k0, uint32_t k1, uint32_t j) {
    uint32_t o0, o1;
    tf2x32(k0, k1, 0u, j, &o0, &o1);
    return o0 ^ o1;
}

// ---------------------------------------------------------------------------
// Packed f32x2 helpers (FFMA2, used by logits GEMM)
// ---------------------------------------------------------------------------
__device__ __forceinline__ unsigned long long pk2(float lo, float hi) {
    unsigned long long r;
    asm("mov.b64 %0, {%1, %2};" : "=l"(r) : "f"(lo), "f"(hi));
    return r;
}
__device__ __forceinline__ void upk2(unsigned long long v, float& lo, float& hi) {
    asm("mov.b64 {%0, %1}, %2;" : "=f"(lo), "=f"(hi) : "l"(v));
}
__device__ __forceinline__ void fma2(unsigned long long& d,
                                     unsigned long long a,
                                     unsigned long long b) {
    asm("fma.rn.f32x2 %0, %1, %2, %0;" : "+l"(d) : "l"(a), "l"(b));
}

// ---------------------------------------------------------------------------
// Tensor-core helpers (mma.sync m16n8k16 fp16 -> fp32)
// ---------------------------------------------------------------------------
__device__ __forceinline__ uint32_t smem_u32(const void* p) {
    return (uint32_t)__cvta_generic_to_shared(p);
}
__device__ __forceinline__ void ldsm_x4(uint32_t* r, uint32_t addr) {
    asm volatile("ldmatrix.sync.aligned.m8n8.x4.shared.b16 {%0,%1,%2,%3}, [%4];"
        : "=r"(r[0]), "=r"(r[1]), "=r"(r[2]), "=r"(r[3]) : "r"(addr));
}
__device__ __forceinline__ void ldsm_x2(uint32_t* r, uint32_t addr) {
    asm volatile("ldmatrix.sync.aligned.m8n8.x2.shared.b16 {%0,%1}, [%2];"
        : "=r"(r[0]), "=r"(r[1]) : "r"(addr));
}
__device__ __forceinline__ void mma16816(float* c, const uint32_t* a,
                                         const uint32_t* b) {
    asm volatile("mma.sync.aligned.m16n8k16.row.col.f32.f16.f16.f32 "
        "{%0,%1,%2,%3}, {%4,%5,%6,%7}, {%8,%9}, {%0,%1,%2,%3};"
        : "+f"(c[0]), "+f"(c[1]), "+f"(c[2]), "+f"(c[3])
        : "r"(a[0]), "r"(a[1]), "r"(a[2]), "r"(a[3]), "r"(b[0]), "r"(b[1]));
}

// ---------------------------------------------------------------------------
// deg: degree count (2 edges/thread)
// ---------------------------------------------------------------------------
__global__ void deg_kernel(const int* __restrict__ dst) {
    int t = blockIdx.x * blockDim.x + threadIdx.x;
    int e0 = t * 2;
    if (e0 >= N_EDGES) return;
    atomicAdd(&g_degi[__ldg(&dst[e0])], 1);
    if (e0 + 1 < N_EDGES) atomicAdd(&g_degi[__ldg(&dst[e0 + 1])], 1);
}

// ---------------------------------------------------------------------------
// scan: rowptr prefix sum; zeroes g_degi after reading (no memset needed).
// ---------------------------------------------------------------------------
__global__ void scan_kernel() {
    __shared__ int sh[1024];
    const int tid = threadIdx.x;
    const int per = 40;
    int base = tid * per;
    int deg_local[per];
    int s = 0;
    if (base < N_NODES) {
        #pragma unroll
        for (int i = 0; i < per; i += 4) {
            int4 d4 = *reinterpret_cast<const int4*>(&g_degi[base + i]);
            deg_local[i + 0] = d4.x; deg_local[i + 1] = d4.y;
            deg_local[i + 2] = d4.z; deg_local[i + 3] = d4.w;
            s += d4.x + d4.y + d4.z + d4.w;
        }
        int4 z = make_int4(0, 0, 0, 0);
        #pragma unroll
        for (int i = 0; i < per; i += 4)
            *reinterpret_cast<int4*>(&g_degi[base + i]) = z;
    }
    sh[tid] = s;
    __syncthreads();
    for (int o = 1; o < 1024; o <<= 1) {
        int v = (tid >= o) ? sh[tid - o] : 0;
        __syncthreads();
        sh[tid] += v;
        __syncthreads();
    }
    int run = (tid > 0) ? sh[tid - 1] : 0;
    if (base < N_NODES) {
        for (int i = 0; i < per; i++) {
            int v = base + i;
            g_rowptr[v] = run;
            g_cursor[v] = run;
            run += deg_local[i];
        }
        if (base + per >= N_NODES) g_rowptr[N_NODES] = run;
    }
}

// ---------------------------------------------------------------------------
// FAT kernel: blocks [0, 1250) = CSR slot fill (latency-bound);
//             blocks [1250, 3750) = dropout(x) -> g_h0h (ALU-bound).
// Disjoint pipes; the ~18us dropout hides the ~14us fill.
// ---------------------------------------------------------------------------
#define FILL_BLOCKS 1250
#define DROP_BLOCKS 2500

__global__ void fat_fill_drop_kernel(const int* __restrict__ src,
                                     const int* __restrict__ dst,
                                     const float* __restrict__ x,
                                     uint32_t k0, uint32_t k1) {
    if (blockIdx.x < FILL_BLOCKS) {
        int t = blockIdx.x * blockDim.x + threadIdx.x;
        int e0 = t * 2;
        if (e0 >= N_EDGES) return;
        int d0 = __ldg(&dst[e0]);
        int s0 = __ldg(&src[e0]);
        int slot0 = atomicAdd(&g_cursor[d0], 1);
        if (e0 + 1 < N_EDGES) {
            int d1 = __ldg(&dst[e0 + 1]);
            int s1 = __ldg(&src[e0 + 1]);
            int slot1 = atomicAdd(&g_cursor[d1], 1);
            g_esrc[slot1] = s1;
        }
        g_esrc[slot0] = s0;
    } else {
        int t = (blockIdx.x - FILL_BLOCKS) * blockDim.x + threadIdx.x;
        int j = t * 8;
        float4 v0 = *reinterpret_cast<const float4*>(x + j);
        float4 v1 = *reinterpret_cast<const float4*>(x + j + 4);
        float f[8] = {v0.x, v0.y, v0.z, v0.w, v1.x, v1.y, v1.z, v1.w};
        __half2 o[4];
        #pragma unroll
        for (int i = 0; i < 4; i++) {
            float a = (pbits(k0, k1, j + 2 * i)     & 0x80000000u) ? 0.0f : f[2 * i]     * 2.0f;
            float b = (pbits(k0, k1, j + 2 * i + 1) & 0x80000000u) ? 0.0f : f[2 * i + 1] * 2.0f;
            o[i] = __floats2half2_rn(a, b);
        }
        *reinterpret_cast<uint4*>(g_h0h + j / 2) =
            *reinterpret_cast<const uint4*>(o);
    }
}

// ---------------------------------------------------------------------------
// AGG kernel (smem-free, high occupancy):
//   agg[v] = (h[v] + sum_{u->v} h[u]) / (deg+1),  fp16 in, fp16 out (fp32 acc)
// One warp per node; lane covers k = 4*lane..4*lane+3.
// ---------------------------------------------------------------------------
__global__ void __launch_bounds__(256)
agg_kernel(const __half2* __restrict__ hin) {
    const int w    = (blockIdx.x * blockDim.x + threadIdx.x) >> 5;
    const int lane = threadIdx.x & 31;
    const int beg = __ldg(&g_rowptr[w]);
    const int end = __ldg(&g_rowptr[w + 1]);
    h2x2 sv = *reinterpret_cast<const h2x2*>(hin + (size_t)w * D2 + 2 * lane);
    float2 s0 = __half22float2(sv.a), s1 = __half22float2(sv.b);
    float4 acc = make_float4(s0.x, s0.y, s1.x, s1.y);
    int i = beg;
    for (; i + 7 < end; i += 8) {
        h2x2 m[8];
        #pragma unroll
        for (int u = 0; u < 8; u++) {
            int s = __ldg(&g_esrc[i + u]);
            m[u] = *reinterpret_cast<const h2x2*>(hin + (size_t)s * D2 + 2 * lane);
        }
        #pragma unroll
        for (int u = 0; u < 8; u++) {
            float2 f0 = __half22float2(m[u].a);
            float2 f1 = __half22float2(m[u].b);
            acc.x += f0.x; acc.y += f0.y;
            acc.z += f1.x; acc.w += f1.y;
        }
    }
    for (; i < end; i++) {
        int s = __ldg(&g_esrc[i]);
        h2x2 m0 = *reinterpret_cast<const h2x2*>(hin + (size_t)s * D2 + 2 * lane);
        float2 f0 = __half22float2(m0.a);
        float2 f1 = __half22float2(m0.b);
        acc.x += f0.x; acc.y += f0.y;
        acc.z += f1.x; acc.w += f1.y;
    }
    float rs = 1.0f / (float)(end - beg + 1);
    h2x2 st;
    st.a = __floats2half2_rn(acc.x * rs, acc.y * rs);
    st.b = __floats2half2_rn(acc.z * rs, acc.w * rs);
    *reinterpret_cast<h2x2*>(g_aggh + (size_t)w * D + 4 * lane) = st;
}

// ---------------------------------------------------------------------------
// Tensor-core layer GEMM (R14-proven):  out[v][c] = A[v].W[c] + bias[c]
// Block 256 thr = 8 warps (2 m x 4 n), tile 64 nodes x 128 cols.
// A: fp16 smem [64][SAP]; W: fp32->fp16 smem [128][SAP].  fp32 accumulators.
// ---------------------------------------------------------------------------
#define GEMM_SMEM ((64 * SAP + 128 * SAP) * 2)

template <int RELU_DROP>
__global__ void __launch_bounds__(256, 2)
gemm_layer_kernel(const float* __restrict__ W,
                  const float* __restrict__ bias,
                  float* __restrict__ out_f,
                  __half2* __restrict__ out_h,
                  uint32_t k0, uint32_t k1) {
    extern __shared__ __half smh[];
    __half* Ash = smh;                 // [64][SAP]
    __half* Wsh = smh + 64 * SAP;      // [128][SAP]

    const int tid    = threadIdx.x;
    const int lane   = tid & 31;
    const int wid    = tid >> 5;
    const int warp_m = wid >> 2;       // 0..1   (32 rows each)
    const int warp_n = wid & 3;        // 0..3   (32 cols each)
    const int base   = blockIdx.x * TILE;

    // W load: fp32 [c][k] -> fp16 smem (float4 -> 2x half2)
    #pragma unroll
    for (int idx = tid * 4; idx < 128 * 128; idx += 256 * 4) {
        float4 w4 = *reinterpret_cast<const float4*>(W + idx);
        int c = idx >> 7, k = idx & 127;
        __half2* p = reinterpret_cast<__half2*>(Wsh + c * SAP + k);
        p[0] = __floats2half2_rn(w4.x, w4.y);
        p[1] = __floats2half2_rn(w4.z, w4.w);
    }
    // A load: 64 rows x 128 halves from g_aggh (uint4 = 8 halves)
    #pragma unroll
    for (int idx = tid; idx < 64 * 16; idx += 256) {
        int r = idx >> 4, c8 = idx & 15;
        uint4 v = *reinterpret_cast<const uint4*>(
            g_aggh + (size_t)(base + r) * D + c8 * 8);
        *reinterpret_cast<uint4*>(Ash + r * SAP + c8 * 8) = v;
    }
    __syncthreads();

    float acc[2][4][4];
    #pragma unroll
    for (int s = 0; s < 2; s++)
        #pragma unroll
        for (int j = 0; j < 4; j++)
            #pragma unroll
            for (int q = 0; q < 4; q++) acc[s][j][q] = 0.0f;

    // ldmatrix base addresses (canonical fragment recipes)
    const int arow = warp_m * 32 + (lane & 15);
    const int acol = (lane >> 4) * 8;
    uint32_t a_addr = smem_u32(Ash + arow * SAP + acol);
    const int brow = warp_n * 32 + (lane & 7);
    const int bcol = ((lane >> 3) & 1) * 8;
    uint32_t b_addr = smem_u32(Wsh + brow * SAP + bcol);

    #pragma unroll
    for (int kt = 0; kt < 8; kt++) {          // K = 8 x 16
        uint32_t a[2][4], b[4][2];
        #pragma unroll
        for (int s = 0; s < 2; s++)
            ldsm_x4(a[s], a_addr + s * (16 * SAP * 2) + kt * 32);
        #pragma unroll
        for (int j = 0; j < 4; j++)
            ldsm_x2(b[j], b_addr + j * (8 * SAP * 2) + kt * 32);
        #pragma unroll
        for (int s = 0; s < 2; s++)
            #pragma unroll
            for (int j = 0; j < 4; j++)
                mma16816(acc[s][j], a[s], b[j]);
    }

    // Epilogue.  c-fragment: rows lane>>2 (+8), cols 2*(lane&3)+{0,1}.
    #pragma unroll
    for (int s = 0; s < 2; s++) {
        #pragma unroll
        for (int j = 0; j < 4; j++) {
            int cbase = warp_n * 32 + j * 8 + 2 * (lane & 3);
            float b0 = __ldg(&bias[cbase]);
            float b1 = __ldg(&bias[cbase + 1]);
            #pragma unroll
            for (int half = 0; half < 2; half++) {
                int v = base + warp_m * 32 + s * 16 + (lane >> 2) + half * 8;
                float r0 = acc[s][j][2 * half + 0] + b0;
                float r1 = acc[s][j][2 * half + 1] + b1;
                if (RELU_DROP) {
                    r0 = fmaxf(r0, 0.0f);
                    r1 = fmaxf(r1, 0.0f);
                    uint32_t j0 = (uint32_t)(v * D + cbase);
                    r0 = (pbits(k0, k1, j0 + 0) & 0x80000000u) ? 0.0f : r0 * 2.0f;
                    r1 = (pbits(k0, k1, j0 + 1) & 0x80000000u) ? 0.0f : r1 * 2.0f;
                    out_h[(size_t)v * D2 + cbase / 2] = __floats2half2_rn(r0, r1);
                } else {
                    *reinterpret_cast<float2*>(out_f + (size_t)v * D + cbase) =
                        make_float2(r0, r1);
                }
            }
        }
    }
}

// ---------------------------------------------------------------------------
// Standalone tiled GEMM (logits, NC=64, fp32 FFMA2; A = fp32 h output)
// ---------------------------------------------------------------------------
#define GEMM64_SMEM ((128 * 68 + 16 * 256) * 4)

__global__ void __launch_bounds__(128)
gemm64_kernel(const float* __restrict__ A,
              const float* __restrict__ W,
              const float* __restrict__ bias,
              float* __restrict__ out) {
    constexpr int NC = 64, NCP = 68, TXN = 16, NTHR = 128;
    extern __shared__ float sm[];
    float* Wt   = sm;                  // [128][68]
    float* AshF = sm + 128 * NCP;      // [16 pairs][128][2]
    const unsigned long long* AshU =
        reinterpret_cast<const unsigned long long*>(AshF);

    const int tid  = threadIdx.x;
    const int tx   = tid % TXN;
    const int ty   = tid / TXN;
    const int base = blockIdx.x * 32;

    for (int idx = tid; idx < NC * 128; idx += NTHR) {
        int c = idx >> 7, k = idx & 127;
        Wt[k * NCP + c] = W[idx];
    }
    for (int idx = tid; idx < 32 * 128; idx += NTHR) {
        int n = idx >> 7, k = idx & 127;
        AshF[(n >> 1) * 256 + 2 * k + (n & 1)] = A[(size_t)(base + n) * D + k];
    }
    __syncthreads();

    unsigned long long acc2[2][4];
    #pragma unroll
    for (int p = 0; p < 2; p++)
        #pragma unroll
        for (int j = 0; j < 4; j++) acc2[p][j] = 0ull;

    const int p0 = ty * 2;
    #pragma unroll 8
    for (int k = 0; k < 128; k += 4) {
        float4 wv[4];
        #pragma unroll
        for (int i = 0; i < 4; i++)
            wv[i] = *reinterpret_cast<const float4*>(&Wt[(k + i) * NCP + 4 * tx]);
        #pragma unroll
        for (int i = 0; i < 4; i++) {
            unsigned long long wd0 = pk2(wv[i].x, wv[i].x);
            unsigned long long wd1 = pk2(wv[i].y, wv[i].y);
            unsigned long long wd2 = pk2(wv[i].z, wv[i].z);
            unsigned long long wd3 = pk2(wv[i].w, wv[i].w);
            #pragma unroll
            for (int p = 0; p < 2; p++) {
                unsigned long long av = AshU[(p0 + p) * 128 + k + i];
                fma2(acc2[p][0], av, wd0);
                fma2(acc2[p][1], av, wd1);
                fma2(acc2[p][2], av, wd2);
                fma2(acc2[p][3], av, wd3);
            }
        }
    }

    float bias4[4];
    #pragma unroll
    for (int j = 0; j < 4; j++) bias4[j] = __ldg(&bias[4 * tx + j]);

    #pragma unroll
    for (int p = 0; p < 2; p++) {
        float lo[4], hi[4];
        #pragma unroll
        for (int j = 0; j < 4; j++) upk2(acc2[p][j], lo[j], hi[j]);
        #pragma unroll
        for (int half = 0; half < 2; half++) {
            int n = ty * 4 + 2 * p + half;
            int v = base + n;
            float4 r;
            float* vals = half ? hi : lo;
            r.x = vals[0] + bias4[0];
            r.y = vals[1] + bias4[1];
            r.z = vals[2] + bias4[2];
            r.w = vals[3] + bias4[3];
            *reinterpret_cast<float4*>(out + (size_t)v * NC + 4 * tx) = r;
        }
    }
}

// ---------------------------------------------------------------------------
// Decoder loss + fused finalize (last-block ticket; self-resets g_acc).
// ---------------------------------------------------------------------------
__global__ void dec_kernel(const int* __restrict__ shuf,
                           float* __restrict__ out) {
    __shared__ float warp_sums[8];
    int warp = threadIdx.x >> 5;
    int lane = threadIdx.x & 31;
    int v = blockIdx.x * 8 + warp;
    float contrib = 0.0f;
    if (v < N_NODES) {
        const float* a = g_logits + (size_t)v * DECD;
        float a0 = a[lane], a1 = a[lane + 32];
        float m = fmaxf(a0, a1);
        #pragma unroll
        for (int off = 16; off; off >>= 1)
            m = fmaxf(m, __shfl_xor_sync(0xffffffffu, m, off));
        float s = expf(a0 - m) + expf(a1 - m);
        #pragma unroll
        for (int off = 16; off; off >>= 1)
            s += __shfl_xor_sync(0xffffffffu, s, off);
        float lse = m + logf(s);
        const float* bp = g_logits + (size_t)__ldg(&shuf[v]) * DECD;
        float b0 = bp[lane], b1 = bp[lane + 32];
        float t = b0 * (a0 - lse) + b1 * (a1 - lse);
        #pragma unroll
        for (int off = 16; off; off >>= 1)
            t += __shfl_xor_sync(0xffffffffu, t, off);
        contrib = -t;
    }
    if (lane == 0) warp_sums[warp] = contrib;
    __syncthreads();
    if (threadIdx.x == 0) {
        float s = 0.0f;
        #pragma unroll
        for (int w = 0; w < 8; w++) s += warp_sums[w];
        atomicAdd(&g_acc, (double)s);
        __threadfence();
        unsigned int t = atomicAdd(&g_ticket, 1u);
        if (t == gridDim.x - 1) {
            out[(size_t)N_NODES * D] = (float)(g_acc / (double)N_NODES);
            g_acc = 0.0;               // self-reset for graph replay
            g_ticket = 0;
        }
    }
}

// ---------------------------------------------------------------------------
// Host launcher (graph-capturable).  Order: deg(1), scan(2),
// fat(fill||dropout)(3), agg(4), gemm1(5), agg(6), gemm2(7), logits(8), dec(9).
// ---------------------------------------------------------------------------
extern "C" void kernel_launch(void* const* d_in, const int* in_sizes, int n_in,
                              void* d_out, int out_size) {
    const float* x    = (const float*)d_in[0];
    const int*   src  = (const int*)  d_in[1];
    const int*   dst  = (const int*)  d_in[2];
    const int*   shuf = (const int*)  d_in[3];
    const float* W1   = (const float*)d_in[4];
    const float* b1   = (const float*)d_in[5];
    const float* W2   = (const float*)d_in[6];
    const float* b2   = (const float*)d_in[7];
    const float* Wd   = (const float*)d_in[8];
    const float* bd   = (const float*)d_in[9];
    float* out = (float*)d_out;

    // JAX partitionable threefry: split(key(42),2) foldlike.
    uint32_t dk0_k0, dk0_k1, dk1_k0, dk1_k1;
    tf2x32(0u, 42u, 0u, 0u, &dk0_k0, &dk0_k1);   // dropout on x
    tf2x32(0u, 42u, 0u, 1u, &dk1_k0, &dk1_k1);   // dropout after relu(layer1)

    void *p_h0h, *p_h1h, *p_logits;
    cudaGetSymbolAddress(&p_h0h,    g_h0h);
    cudaGetSymbolAddress(&p_h1h,    g_h1h);
    cudaGetSymbolAddress(&p_logits, g_logits);

    cudaFuncSetAttribute((const void*)gemm_layer_kernel<1>,
                         cudaFuncAttributeMaxDynamicSharedMemorySize, GEMM_SMEM);
    cudaFuncSetAttribute((const void*)gemm_layer_kernel<0>,
                         cudaFuncAttributeMaxDynamicSharedMemorySize, GEMM_SMEM);
    cudaFuncSetAttribute((const void*)gemm64_kernel,
                         cudaFuncAttributeMaxDynamicSharedMemorySize, GEMM64_SMEM);

    // 1: degree count (g_degi zeroed by previous scan run)
    deg_kernel<<<(N_EDGES / 2 + 255) / 256, 256>>>(dst);
    // 2: rowptr scan (also zeroes g_degi for next replay)
    scan_kernel<<<1, 1024>>>();
    // 3: CSR slot fill || dropout(x) -> g_h0h  (overlapped pipes)
    fat_fill_drop_kernel<<<FILL_BLOCKS + DROP_BLOCKS, 256>>>(
        src, dst, x, dk0_k0, dk0_k1);
    // 4: layer 1 aggregate -> g_aggh (fp16)
    agg_kernel<<<N_NODES / 8, 256>>>((const __half2*)p_h0h);
    // 5: layer 1 GEMM (tensor core) + relu + dropout -> g_h1h (fp16)
    gemm_layer_kernel<1><<<N_NODES / TILE, 256, GEMM_SMEM>>>(
        W1, b1, nullptr, (__half2*)p_h1h, dk1_k0, dk1_k1);
    // 6: layer 2 aggregate
    agg_kernel<<<N_NODES / 8, 256>>>((const __half2*)p_h1h);
    // 7: layer 2 GEMM (tensor core) -> out (fp32)
    gemm_layer_kernel<0><<<N_NODES / TILE, 256, GEMM_SMEM>>>(
        W2, b2, out, nullptr, 0u, 0u);
    // 8: logits
    gemm64_kernel<<<N_NODES / 32, 128, GEMM64_SMEM>>>(out, Wd, bd, (float*)p_logits);
    // 9: decoder loss + finalize (self-resets g_acc / g_ticket)
    dec_kernel<<<N_NODES / 8, 256>>>(shuf, out);
}